// round 1
// baseline (speedup 1.0000x reference)
#include <cuda_runtime.h>
#include <math.h>

// Analytic gradient of the "canyon" potential.
//
// Per point (x, y), with K uniform rays thetas[k] = 2*pi*k/K and sector
// middles at (2m+1)*pi/K:
//   phi  = atan2(y, x) mapped to [0, 2pi)
//   n    = round(phi * K / (2pi));  dphi = phi - n*(2pi/K)   in [-pi/K, pi/K]
//   d    = pi/K - |dphi|           (distance to nearest middle)
//   g(d) = smoothstep(d; inner=pi/4K, outer=pi/2K)  == (1 - w) of the reference
//   pot  = 0.5*a*r2 + g * 0.5*b*r2*dphi^2
// theta_star (from argmin over thetas) is piecewise constant w.r.t. xy, so it
// contributes no gradient. Using dphi/dx = -y/r2, dphi/dy = x/r2 and
// dd/dphi = -sign(dphi):
//   coef   = a + b*g*dphi^2
//   common = 0.5*b*(dphi^2 * g'(d) * s + 2*g*dphi),  s = -sign(dphi)
//   grad   = (coef*x - common*y, coef*y + common*x)
// Output = -grad, and exactly 0 at the origin.

struct Params {
    float a, b;
    float k_over_2pi;  // K / (2*pi)
    float step;        // 2*pi / K
    float P;           // pi / K
    float inner;       // pi / (4K)
    float inv_band;    // 1 / (outer - inner) = 4K / pi
};

__device__ __forceinline__ void point_grad(float x, float y,
                                           float a, float b,
                                           float k_over_2pi, float step,
                                           float P, float inner, float inv_band,
                                           float& ox, float& oy)
{
    float phi = atan2f(y, x);
    if (phi < 0.0f) phi += 6.2831853071795864769f;

    float n    = rintf(phi * k_over_2pi);
    float dphi = fmaf(-n, step, phi);          // wrapped to [-pi/K, pi/K]
    float d    = P - fabsf(dphi);

    float t = (d - inner) * inv_band;
    t = fminf(fmaxf(t, 0.0f), 1.0f);
    float g  = t * t * (3.0f - 2.0f * t);
    float gp = 6.0f * t * (1.0f - t) * inv_band;   // dg/dd (0 at t=0 and t=1)

    float s     = (dphi >= 0.0f) ? -1.0f : 1.0f;   // dd/dphi
    float dphi2 = dphi * dphi;

    float common = 0.5f * b * (dphi2 * gp * s + 2.0f * g * dphi);
    float coef   = fmaf(b * g, dphi2, a);

    float gx = coef * x - common * y;
    float gy = coef * y + common * x;

    if (x == 0.0f && y == 0.0f) { gx = 0.0f; gy = 0.0f; }

    ox = -gx;
    oy = -gy;
}

__global__ void canyon_grad_kernel(const float* __restrict__ xy,
                                   float* __restrict__ out,
                                   const float* __restrict__ a_ptr,
                                   const float* __restrict__ b_ptr,
                                   int ntot,          // total floats (2*N)
                                   float k_over_2pi, float step,
                                   float P, float inner, float inv_band)
{
    int i = blockIdx.x * blockDim.x + threadIdx.x;
    int base = i * 4;
    if (base >= ntot) return;

    float a = fminf(fmaxf(__ldg(a_ptr), 0.0f), 20.0f);
    float b = fminf(fmaxf(__ldg(b_ptr), 0.0f), 20.0f);

    if (base + 3 < ntot) {
        // Fast path: one float4 = two (x,y) points, 128-bit ld/st.
        float4 v = *reinterpret_cast<const float4*>(xy + base);
        float4 r;
        point_grad(v.x, v.y, a, b, k_over_2pi, step, P, inner, inv_band, r.x, r.y);
        point_grad(v.z, v.w, a, b, k_over_2pi, step, P, inner, inv_band, r.z, r.w);
        *reinterpret_cast<float4*>(out + base) = r;
    } else {
        // Tail: handle remaining whole points (element count is always even).
        for (int e = base; e + 1 < ntot; e += 2) {
            float ox, oy;
            point_grad(xy[e], xy[e + 1], a, b, k_over_2pi, step, P, inner, inv_band, ox, oy);
            out[e]     = ox;
            out[e + 1] = oy;
        }
    }
}

extern "C" void kernel_launch(void* const* d_in, const int* in_sizes, int n_in,
                              void* d_out, int out_size)
{
    const float* xy     = (const float*)d_in[0];
    const float* a_ptr  = (const float*)d_in[2];
    const float* b_ptr  = (const float*)d_in[3];
    float* out          = (float*)d_out;

    int ntot = in_sizes[0];      // 2*N floats
    int K    = in_sizes[1];      // number of rays

    double PI = 3.14159265358979323846;
    float k_over_2pi = (float)((double)K / (2.0 * PI));
    float step       = (float)(2.0 * PI / (double)K);
    float P          = (float)(PI / (double)K);
    float inner      = (float)(PI / (4.0 * (double)K));
    float inv_band   = (float)(4.0 * (double)K / PI);

    int n4     = (ntot + 3) / 4;       // one thread per float4 (2 points)
    int threads = 256;
    int blocks  = (n4 + threads - 1) / threads;

    canyon_grad_kernel<<<blocks, threads>>>(xy, out, a_ptr, b_ptr, ntot,
                                            k_over_2pi, step, P, inner, inv_band);
}

// round 7
// speedup vs baseline: 1.2905x; 1.2905x over previous
#include <cuda_runtime.h>
#include <math.h>

// Analytic gradient of the "canyon" potential (round-1 derivation, validated
// at rel_err 3.9e-6):
//   coef   = a + b*g*dphi^2
//   common = b*dphi*(g - 0.5*g'(d)*|dphi|)        [s*dphi^2 == -dphi*|dphi|]
//   out    = -(coef*x - common*y, coef*y + common*x), 0 at origin
//
// K==8 fast path: rays every 45 deg. Branchless octant fold (exact 180 deg sign
// fold + up to two 45 deg rotations with sqrt(2)/2) brings the point to
// |angle| <= 22.5 deg of its nearest ray; dphi is invariant under all folds
// (they are multiples of the ray spacing). Then dphi = atan(y'/x') via a
// degree-9 odd Taylor poly on |u| <= tan(22.5 deg) (abs err <= 5.6e-6).

__device__ __forceinline__ void point_grad_fast(float x0, float y0,
                                                float a, float b,
                                                float P, float inner,
                                                float inv_band, float c3ib,
                                                float& ox, float& oy)
{
    const float C45 = 0.70710678118654752440f;   // sqrt(2)/2
    const float T22 = 0.41421356237309504880f;   // tan(pi/8)

    // 180-degree fold: x >= 0 afterwards (dphi invariant)
    float s0 = copysignf(1.0f, x0);
    float x  = fabsf(x0);
    float y  = y0 * s0;

    // Stage 1: if |y| > x, rotate by -sign(y)*45deg  -> angle in [-45, 45]
    {
        float sy = copysignf(C45, y);
        float xr = fmaf(sy, y, C45 * x);
        float yr = fmaf(-sy, x, C45 * y);
        bool  c  = fabsf(y) > x;
        x = c ? xr : x;
        y = c ? yr : y;
    }
    // Stage 2: if |y| > tan(22.5)*x, rotate again -> angle in [-22.5, 22.5]
    {
        float sy = copysignf(C45, y);
        float xr = fmaf(sy, y, C45 * x);
        float yr = fmaf(-sy, x, C45 * y);
        bool  c  = fabsf(y) > T22 * x;
        x = c ? xr : x;
        y = c ? yr : y;
    }

    // dphi = atan(y/x), |y/x| <= ~0.4142
    float u  = __fdividef(y, x);
    float u2 = u * u;
    float p  = fmaf(u2, fmaf(u2, fmaf(u2, fmaf(u2, 0.11111111f, -0.14285714f),
                                      0.2f), -0.33333333f), 1.0f);
    float dphi = u * p;

    float ad = fabsf(dphi);
    float d  = P - ad;                         // distance to nearest middle
    float t  = __saturatef((d - inner) * inv_band);
    float g  = t * t * fmaf(-2.0f, t, 3.0f);   // smoothstep
    float gph = c3ib * (t * (1.0f - t));       // 0.5 * dg/dd

    float dphi2  = dphi * dphi;
    float bd     = b * dphi;
    float common = bd * fmaf(-gph, ad, g);
    float ncoef  = -fmaf(b * g, dphi2, a);     // -coef

    ox = fmaf(common, y0, ncoef * x0);         // = -(coef*x - common*y)
    oy = fmaf(-common, x0, ncoef * y0);        // = -(coef*y + common*x)

    if (x0 == 0.0f && y0 == 0.0f) { ox = 0.0f; oy = 0.0f; }
}

__global__ void canyon_grad_k8_kernel(const float* __restrict__ xy,
                                      float* __restrict__ out,
                                      const float* __restrict__ a_ptr,
                                      const float* __restrict__ b_ptr,
                                      int ntot,
                                      float P, float inner,
                                      float inv_band, float c3ib)
{
    int i = blockIdx.x * blockDim.x + threadIdx.x;
    int base = i * 4;
    if (base >= ntot) return;

    float a = fminf(fmaxf(__ldg(a_ptr), 0.0f), 20.0f);
    float b = fminf(fmaxf(__ldg(b_ptr), 0.0f), 20.0f);

    if (base + 3 < ntot) {
        float4 v = *reinterpret_cast<const float4*>(xy + base);
        float4 r;
        point_grad_fast(v.x, v.y, a, b, P, inner, inv_band, c3ib, r.x, r.y);
        point_grad_fast(v.z, v.w, a, b, P, inner, inv_band, c3ib, r.z, r.w);
        *reinterpret_cast<float4*>(out + base) = r;
    } else {
        for (int e = base; e + 1 < ntot; e += 2) {
            float ox, oy;
            point_grad_fast(xy[e], xy[e + 1], a, b, P, inner, inv_band, c3ib, ox, oy);
            out[e]     = ox;
            out[e + 1] = oy;
        }
    }
}

// ---------- generic fallback (any K), same as validated round-1 kernel ----------
__device__ __forceinline__ void point_grad_gen(float x, float y,
                                               float a, float b,
                                               float k_over_2pi, float step,
                                               float P, float inner, float inv_band,
                                               float& ox, float& oy)
{
    float phi = atan2f(y, x);
    if (phi < 0.0f) phi += 6.2831853071795864769f;
    float n    = rintf(phi * k_over_2pi);
    float dphi = fmaf(-n, step, phi);
    float d    = P - fabsf(dphi);
    float t = __saturatef((d - inner) * inv_band);
    float g  = t * t * (3.0f - 2.0f * t);
    float gp = 6.0f * t * (1.0f - t) * inv_band;
    float s     = (dphi >= 0.0f) ? -1.0f : 1.0f;
    float dphi2 = dphi * dphi;
    float common = 0.5f * b * (dphi2 * gp * s + 2.0f * g * dphi);
    float coef   = fmaf(b * g, dphi2, a);
    float gx = coef * x - common * y;
    float gy = coef * y + common * x;
    if (x == 0.0f && y == 0.0f) { gx = 0.0f; gy = 0.0f; }
    ox = -gx; oy = -gy;
}

__global__ void canyon_grad_gen_kernel(const float* __restrict__ xy,
                                       float* __restrict__ out,
                                       const float* __restrict__ a_ptr,
                                       const float* __restrict__ b_ptr,
                                       int ntot,
                                       float k_over_2pi, float step,
                                       float P, float inner, float inv_band)
{
    int i = blockIdx.x * blockDim.x + threadIdx.x;
    int base = i * 4;
    if (base >= ntot) return;
    float a = fminf(fmaxf(__ldg(a_ptr), 0.0f), 20.0f);
    float b = fminf(fmaxf(__ldg(b_ptr), 0.0f), 20.0f);
    if (base + 3 < ntot) {
        float4 v = *reinterpret_cast<const float4*>(xy + base);
        float4 r;
        point_grad_gen(v.x, v.y, a, b, k_over_2pi, step, P, inner, inv_band, r.x, r.y);
        point_grad_gen(v.z, v.w, a, b, k_over_2pi, step, P, inner, inv_band, r.z, r.w);
        *reinterpret_cast<float4*>(out + base) = r;
    } else {
        for (int e = base; e + 1 < ntot; e += 2) {
            float ox, oy;
            point_grad_gen(xy[e], xy[e + 1], a, b, k_over_2pi, step, P, inner, inv_band, ox, oy);
            out[e] = ox; out[e + 1] = oy;
        }
    }
}

extern "C" void kernel_launch(void* const* d_in, const int* in_sizes, int n_in,
                              void* d_out, int out_size)
{
    const float* xy    = (const float*)d_in[0];
    const float* a_ptr = (const float*)d_in[2];
    const float* b_ptr = (const float*)d_in[3];
    float* out         = (float*)d_out;

    int ntot = in_sizes[0];
    int K    = in_sizes[1];

    double PI = 3.14159265358979323846;
    float P        = (float)(PI / (double)K);
    float inner    = (float)(PI / (4.0 * (double)K));
    float inv_band = (float)(4.0 * (double)K / PI);
    float c3ib     = 3.0f * inv_band;

    int n4      = (ntot + 3) / 4;
    int threads = 256;
    int blocks  = (n4 + threads - 1) / threads;

    if (K == 8) {
        canyon_grad_k8_kernel<<<blocks, threads>>>(xy, out, a_ptr, b_ptr, ntot,
                                                   P, inner, inv_band, c3ib);
    } else {
        float k_over_2pi = (float)((double)K / (2.0 * PI));
        float step       = (float)(2.0 * PI / (double)K);
        canyon_grad_gen_kernel<<<blocks, threads>>>(xy, out, a_ptr, b_ptr, ntot,
                                                    k_over_2pi, step, P, inner, inv_band);
    }
}

// round 8
// speedup vs baseline: 1.3664x; 1.0588x over previous
#include <cuda_runtime.h>
#include <math.h>

// Analytic gradient of the "canyon" potential (round-1 derivation, validated):
//   coef   = a + b*g*dphi^2
//   common = b*dphi*(g - 0.5*g'(d)*|dphi|)
//   out    = -(coef*x - common*y, coef*y + common*x), 0 at origin
//
// K==8 fast path. Fold to the first octant with abs/min/max: each reflection
// used (x<0, y<0, swap when |y|>|x|) is about a multiple of the ray spacing
// pi/4, so each flips sign(dphi); net sign = XOR of three sign bits.
// If m > tan(22.5)*M use atan(u) - pi/4 = atan((m-M)/(m+M)) exactly, so a
// single division feeds one deg-9 odd poly on |u| <= tan(pi/8) (err <= 5.6e-6).
// t = saturate(3 - inv_band*|dphi|): (P-inner)*inv_band == 3 identically.

__device__ float2 g_ab;   // clipped (a, b), written by prologue kernel

__global__ void clip_ab_kernel(const float* __restrict__ a_ptr,
                               const float* __restrict__ b_ptr)
{
    if (threadIdx.x == 0 && blockIdx.x == 0) {
        g_ab.x = fminf(fmaxf(*a_ptr, 0.0f), 20.0f);
        g_ab.y = fminf(fmaxf(*b_ptr, 0.0f), 20.0f);
    }
}

__device__ __forceinline__ void point_grad_fast(float x0, float y0,
                                                float a, float b,
                                                float inv_band, float c3ib,
                                                float& ox, float& oy)
{
    const float T22 = 0.41421356237309504880f;   // tan(pi/8)

    float ax = fabsf(x0);
    float ay = fabsf(y0);
    float M  = fmaxf(ax, ay);
    float m  = fminf(ax, ay);

    // second fold via atan identity: atan(m/M) - pi/4 = atan((m-M)/(m+M))
    bool  c   = m > T22 * M;
    float num = c ? (m - M) : m;
    float den = c ? (m + M) : M;

    float u  = __fdividef(num, den);             // |u| <= tan(pi/8)
    float u2 = u * u;
    float p  = fmaf(u2, fmaf(u2, fmaf(u2, fmaf(u2, 0.11111111f, -0.14285714f),
                                      0.2f), -0.33333333f), 1.0f);
    float d1 = u * p;                            // signed dphi in folded frame

    // net reflection sign: (x<0) xor (y<0) xor (ay>ax)
    unsigned sb = (__float_as_uint(x0) ^ __float_as_uint(y0)) & 0x80000000u;
    if (ay > ax) sb ^= 0x80000000u;
    float dphi = __uint_as_float(__float_as_uint(d1) ^ sb);

    float ad = fabsf(dphi);
    float t  = __saturatef(fmaf(-inv_band, ad, 3.0f));   // (P-inner)*inv_band == 3
    float tt = t * t;
    float g  = tt * fmaf(-2.0f, t, 3.0f);        // smoothstep
    float gph = c3ib * fmaf(-t, t, t);           // 0.5*dg/dd = 3*inv_band*t*(1-t)

    float common = (b * dphi) * fmaf(-gph, ad, g);
    float coef   = fmaf(b * g, dphi * dphi, a);

    float cx = coef * x0;
    float cy = coef * y0;
    ox = fmaf(common,  y0, -cx);                 // -(coef*x - common*y)
    oy = fmaf(-common, x0, -cy);                 // -(coef*y + common*x)

    if (M == 0.0f) { ox = 0.0f; oy = 0.0f; }     // origin (both exactly zero)
}

__global__ void canyon_grad_k8_kernel(const float4* __restrict__ xy4,
                                      float4* __restrict__ out4,
                                      const float* __restrict__ xy,
                                      float* __restrict__ out,
                                      int n4, int ntot,
                                      float inv_band, float c3ib)
{
    int gid  = blockIdx.x * blockDim.x + threadIdx.x;
    int lane = threadIdx.x & 31;
    int wid  = gid >> 5;
    int i0   = wid * 64 + lane;     // warp covers float4s [wid*64, wid*64+64)
    int i1   = i0 + 32;

    float2 ab = g_ab;
    float a = ab.x, b = ab.y;

    if (i0 < n4) {
        float4 v = xy4[i0];
        float4 r;
        point_grad_fast(v.x, v.y, a, b, inv_band, c3ib, r.x, r.y);
        point_grad_fast(v.z, v.w, a, b, inv_band, c3ib, r.z, r.w);
        out4[i0] = r;
    }
    if (i1 < n4) {
        float4 v = xy4[i1];
        float4 r;
        point_grad_fast(v.x, v.y, a, b, inv_band, c3ib, r.x, r.y);
        point_grad_fast(v.z, v.w, a, b, inv_band, c3ib, r.z, r.w);
        out4[i1] = r;
    }

    // residual pair when ntot % 4 == 2 (N odd)
    if (gid == 0 && (ntot & 3)) {
        int e = n4 * 4;
        float ox, oy;
        point_grad_fast(xy[e], xy[e + 1], a, b, inv_band, c3ib, ox, oy);
        out[e] = ox; out[e + 1] = oy;
    }
}

// ---------- generic fallback (any K), validated round-1 path ----------
__device__ __forceinline__ void point_grad_gen(float x, float y,
                                               float a, float b,
                                               float k_over_2pi, float step,
                                               float P, float inner, float inv_band,
                                               float& ox, float& oy)
{
    float phi = atan2f(y, x);
    if (phi < 0.0f) phi += 6.2831853071795864769f;
    float n    = rintf(phi * k_over_2pi);
    float dphi = fmaf(-n, step, phi);
    float d    = P - fabsf(dphi);
    float t = __saturatef((d - inner) * inv_band);
    float g  = t * t * (3.0f - 2.0f * t);
    float gp = 6.0f * t * (1.0f - t) * inv_band;
    float s     = (dphi >= 0.0f) ? -1.0f : 1.0f;
    float dphi2 = dphi * dphi;
    float common = 0.5f * b * (dphi2 * gp * s + 2.0f * g * dphi);
    float coef   = fmaf(b * g, dphi2, a);
    float gx = coef * x - common * y;
    float gy = coef * y + common * x;
    if (x == 0.0f && y == 0.0f) { gx = 0.0f; gy = 0.0f; }
    ox = -gx; oy = -gy;
}

__global__ void canyon_grad_gen_kernel(const float* __restrict__ xy,
                                       float* __restrict__ out,
                                       const float* __restrict__ a_ptr,
                                       const float* __restrict__ b_ptr,
                                       int ntot,
                                       float k_over_2pi, float step,
                                       float P, float inner, float inv_band)
{
    int i = blockIdx.x * blockDim.x + threadIdx.x;
    int base = i * 4;
    if (base >= ntot) return;
    float a = fminf(fmaxf(__ldg(a_ptr), 0.0f), 20.0f);
    float b = fminf(fmaxf(__ldg(b_ptr), 0.0f), 20.0f);
    if (base + 3 < ntot) {
        float4 v = *reinterpret_cast<const float4*>(xy + base);
        float4 r;
        point_grad_gen(v.x, v.y, a, b, k_over_2pi, step, P, inner, inv_band, r.x, r.y);
        point_grad_gen(v.z, v.w, a, b, k_over_2pi, step, P, inner, inv_band, r.z, r.w);
        *reinterpret_cast<float4*>(out + base) = r;
    } else {
        for (int e = base; e + 1 < ntot; e += 2) {
            float ox, oy;
            point_grad_gen(xy[e], xy[e + 1], a, b, k_over_2pi, step, P, inner, inv_band, ox, oy);
            out[e] = ox; out[e + 1] = oy;
        }
    }
}

extern "C" void kernel_launch(void* const* d_in, const int* in_sizes, int n_in,
                              void* d_out, int out_size)
{
    const float* xy    = (const float*)d_in[0];
    const float* a_ptr = (const float*)d_in[2];
    const float* b_ptr = (const float*)d_in[3];
    float* out         = (float*)d_out;

    int ntot = in_sizes[0];
    int K    = in_sizes[1];

    double PI = 3.14159265358979323846;
    float P        = (float)(PI / (double)K);
    float inner    = (float)(PI / (4.0 * (double)K));
    float inv_band = (float)(4.0 * (double)K / PI);
    float c3ib     = 3.0f * inv_band;

    if (K == 8) {
        clip_ab_kernel<<<1, 32>>>(a_ptr, b_ptr);

        int n4 = ntot >> 2;                         // whole float4s
        int nwarp = (n4 + 63) / 64;                 // 64 float4s per warp
        long long nthreads = (long long)nwarp * 32;
        if (nthreads == 0) nthreads = 32;           // still need residual handler
        int threads = 256;
        int blocks  = (int)((nthreads + threads - 1) / threads);

        canyon_grad_k8_kernel<<<blocks, threads>>>(
            (const float4*)xy, (float4*)out, xy, out,
            n4, ntot, inv_band, c3ib);
    } else {
        float k_over_2pi = (float)((double)K / (2.0 * PI));
        float step       = (float)(2.0 * PI / (double)K);
        int n4      = (ntot + 3) / 4;
        int threads = 256;
        int blocks  = (n4 + threads - 1) / threads;
        canyon_grad_gen_kernel<<<blocks, threads>>>(xy, out, a_ptr, b_ptr, ntot,
                                                    k_over_2pi, step, P, inner, inv_band);
    }
}

// round 10
// speedup vs baseline: 1.3986x; 1.0236x over previous
#include <cuda_runtime.h>
#include <math.h>

// Analytic gradient of the "canyon" potential (round-1 derivation, validated):
//   coef   = a + b*g*dphi^2
//   common = b*dphi*(g - 0.5*g'(d)*|dphi|)
//   out    = -(coef*x - common*y, coef*y + common*x), 0 at origin
//
// K==8 fast path. Fold to the first octant with abs/min/max: each reflection
// used (x<0, y<0, swap when |y|>|x|) is about a multiple of the ray spacing
// pi/4, so each flips sign(dphi); net sign = XOR of three sign bits.
// If m > tan(22.5)*M use atan(u) - pi/4 = atan((m-M)/(m+M)) exactly, so a
// single division feeds one deg-9 odd poly on |u| <= tan(pi/8) (err <= 5.6e-6).
// t = saturate(3 - inv_band*|dphi|): (P-inner)*inv_band == 3 identically.

__device__ __forceinline__ void point_grad_fast(float x0, float y0,
                                                float a, float b,
                                                float inv_band, float c3ib,
                                                float& ox, float& oy)
{
    const float T22 = 0.41421356237309504880f;   // tan(pi/8)

    float ax = fabsf(x0);
    float ay = fabsf(y0);
    float M  = fmaxf(ax, ay);
    float m  = fminf(ax, ay);

    // second fold via atan identity: atan(m/M) - pi/4 = atan((m-M)/(m+M))
    bool  c   = m > T22 * M;
    float num = c ? (m - M) : m;
    float den = c ? (m + M) : M;

    float u  = __fdividef(num, den);             // |u| <= tan(pi/8)
    float u2 = u * u;
    float p  = fmaf(u2, fmaf(u2, fmaf(u2, fmaf(u2, 0.11111111f, -0.14285714f),
                                      0.2f), -0.33333333f), 1.0f);
    float d1 = u * p;                            // signed dphi in folded frame

    // net reflection sign: (x<0) xor (y<0) xor (ay>ax)
    unsigned sb = (__float_as_uint(x0) ^ __float_as_uint(y0)) & 0x80000000u;
    if (ay > ax) sb ^= 0x80000000u;
    float dphi = __uint_as_float(__float_as_uint(d1) ^ sb);

    float ad = fabsf(dphi);
    float t  = __saturatef(fmaf(-inv_band, ad, 3.0f));   // (P-inner)*inv_band == 3
    float tt = t * t;
    float g  = tt * fmaf(-2.0f, t, 3.0f);        // smoothstep
    float gph = c3ib * fmaf(-t, t, t);           // 0.5*dg/dd = 3*inv_band*t*(1-t)

    float common = (b * dphi) * fmaf(-gph, ad, g);
    float coef   = fmaf(b * g, dphi * dphi, a);

    float cx = coef * x0;
    float cy = coef * y0;
    ox = fmaf(common,  y0, -cx);                 // -(coef*x - common*y)
    oy = fmaf(-common, x0, -cy);                 // -(coef*y + common*x)

    if (M == 0.0f) { ox = 0.0f; oy = 0.0f; }     // origin (both exactly zero)
}

__global__ void canyon_grad_k8_kernel(const float4* __restrict__ xy4,
                                      float4* __restrict__ out4,
                                      const float* __restrict__ xy,
                                      float* __restrict__ out,
                                      const float* __restrict__ a_ptr,
                                      const float* __restrict__ b_ptr,
                                      int n4, int ntot,
                                      float inv_band, float c3ib)
{
    int gid  = blockIdx.x * blockDim.x + threadIdx.x;
    int lane = threadIdx.x & 31;
    int wid  = gid >> 5;
    int base = wid * 128 + lane;    // warp covers float4s [wid*128, wid*128+128)

    // broadcast loads (single address) + clamp, amortized over 8 points
    float a = fminf(fmaxf(__ldg(a_ptr), 0.0f), 20.0f);
    float b = fminf(fmaxf(__ldg(b_ptr), 0.0f), 20.0f);

    #pragma unroll
    for (int j = 0; j < 4; j++) {
        int i = base + j * 32;
        if (i < n4) {
            float4 v = xy4[i];
            float4 r;
            point_grad_fast(v.x, v.y, a, b, inv_band, c3ib, r.x, r.y);
            point_grad_fast(v.z, v.w, a, b, inv_band, c3ib, r.z, r.w);
            out4[i] = r;
        }
    }

    // residual pair when ntot % 4 == 2 (N odd)
    if (gid == 0 && (ntot & 3)) {
        int e = n4 * 4;
        float ox, oy;
        point_grad_fast(xy[e], xy[e + 1], a, b, inv_band, c3ib, ox, oy);
        out[e] = ox; out[e + 1] = oy;
    }
}

// ---------- generic fallback (any K), validated round-1 path ----------
__device__ __forceinline__ void point_grad_gen(float x, float y,
                                               float a, float b,
                                               float k_over_2pi, float step,
                                               float P, float inner, float inv_band,
                                               float& ox, float& oy)
{
    float phi = atan2f(y, x);
    if (phi < 0.0f) phi += 6.2831853071795864769f;
    float n    = rintf(phi * k_over_2pi);
    float dphi = fmaf(-n, step, phi);
    float d    = P - fabsf(dphi);
    float t = __saturatef((d - inner) * inv_band);
    float g  = t * t * (3.0f - 2.0f * t);
    float gp = 6.0f * t * (1.0f - t) * inv_band;
    float s     = (dphi >= 0.0f) ? -1.0f : 1.0f;
    float dphi2 = dphi * dphi;
    float common = 0.5f * b * (dphi2 * gp * s + 2.0f * g * dphi);
    float coef   = fmaf(b * g, dphi2, a);
    float gx = coef * x - common * y;
    float gy = coef * y + common * x;
    if (x == 0.0f && y == 0.0f) { gx = 0.0f; gy = 0.0f; }
    ox = -gx; oy = -gy;
}

__global__ void canyon_grad_gen_kernel(const float* __restrict__ xy,
                                       float* __restrict__ out,
                                       const float* __restrict__ a_ptr,
                                       const float* __restrict__ b_ptr,
                                       int ntot,
                                       float k_over_2pi, float step,
                                       float P, float inner, float inv_band)
{
    int i = blockIdx.x * blockDim.x + threadIdx.x;
    int base = i * 4;
    if (base >= ntot) return;
    float a = fminf(fmaxf(__ldg(a_ptr), 0.0f), 20.0f);
    float b = fminf(fmaxf(__ldg(b_ptr), 0.0f), 20.0f);
    if (base + 3 < ntot) {
        float4 v = *reinterpret_cast<const float4*>(xy + base);
        float4 r;
        point_grad_gen(v.x, v.y, a, b, k_over_2pi, step, P, inner, inv_band, r.x, r.y);
        point_grad_gen(v.z, v.w, a, b, k_over_2pi, step, P, inner, inv_band, r.z, r.w);
        *reinterpret_cast<float4*>(out + base) = r;
    } else {
        for (int e = base; e + 1 < ntot; e += 2) {
            float ox, oy;
            point_grad_gen(xy[e], xy[e + 1], a, b, k_over_2pi, step, P, inner, inv_band, ox, oy);
            out[e] = ox; out[e + 1] = oy;
        }
    }
}

extern "C" void kernel_launch(void* const* d_in, const int* in_sizes, int n_in,
                              void* d_out, int out_size)
{
    const float* xy    = (const float*)d_in[0];
    const float* a_ptr = (const float*)d_in[2];
    const float* b_ptr = (const float*)d_in[3];
    float* out         = (float*)d_out;

    int ntot = in_sizes[0];
    int K    = in_sizes[1];

    double PI = 3.14159265358979323846;
    float P        = (float)(PI / (double)K);
    float inner    = (float)(PI / (4.0 * (double)K));
    float inv_band = (float)(4.0 * (double)K / PI);
    float c3ib     = 3.0f * inv_band;

    if (K == 8) {
        int n4 = ntot >> 2;                          // whole float4s
        int nwarp = (n4 + 127) / 128;                // 128 float4s per warp
        long long nthreads = (long long)nwarp * 32;
        if (nthreads == 0) nthreads = 32;            // residual-only case
        int threads = 256;
        int blocks  = (int)((nthreads + threads - 1) / threads);

        canyon_grad_k8_kernel<<<blocks, threads>>>(
            (const float4*)xy, (float4*)out, xy, out, a_ptr, b_ptr,
            n4, ntot, inv_band, c3ib);
    } else {
        float k_over_2pi = (float)((double)K / (2.0 * PI));
        float step       = (float)(2.0 * PI / (double)K);
        int n4      = (ntot + 3) / 4;
        int threads = 256;
        int blocks  = (n4 + threads - 1) / threads;
        canyon_grad_gen_kernel<<<blocks, threads>>>(xy, out, a_ptr, b_ptr, ntot,
                                                    k_over_2pi, step, P, inner, inv_band);
    }
}

// round 12
// speedup vs baseline: 1.4002x; 1.0012x over previous
#include <cuda_runtime.h>
#include <math.h>

// Analytic gradient of the "canyon" potential (round-1 derivation, validated):
//   coef   = a + b*g*dphi^2
//   common = b*dphi*(g - 0.5*g'(d)*|dphi|)
//   out    = -(coef*x - common*y, coef*y + common*x), 0 at origin
//
// K==8 fast path. Fold to the first octant with abs/min/max: each reflection
// used (x<0, y<0, swap when |y|>|x|) is about a multiple of the ray spacing
// pi/4, so each flips sign(dphi); net sign = XOR of three sign bits.
// If m > tan(22.5)*M use atan(u) - pi/4 = atan((m-M)/(m+M)) exactly, so a
// single division feeds one deg-9 odd poly on |u| <= tan(pi/8) (err <= 5.6e-6).
// t = saturate(3 - inv_band*|dphi|): (P-inner)*inv_band == 3 identically.
//
// R11: explicit 4x LDG.128 front-batching (MLP=4) — R10's loop form compiled
// to serialized load->compute->store (regs=23), leaving DRAM latency exposed.

__device__ __forceinline__ void point_grad_fast(float x0, float y0,
                                                float a, float b,
                                                float inv_band, float c3ib,
                                                float& ox, float& oy)
{
    const float T22 = 0.41421356237309504880f;   // tan(pi/8)

    float ax = fabsf(x0);
    float ay = fabsf(y0);
    float M  = fmaxf(ax, ay);
    float m  = fminf(ax, ay);

    // second fold via atan identity: atan(m/M) - pi/4 = atan((m-M)/(m+M))
    bool  c   = m > T22 * M;
    float num = c ? (m - M) : m;
    float den = c ? (m + M) : M;

    float u  = __fdividef(num, den);             // |u| <= tan(pi/8)
    float u2 = u * u;
    float p  = fmaf(u2, fmaf(u2, fmaf(u2, fmaf(u2, 0.11111111f, -0.14285714f),
                                      0.2f), -0.33333333f), 1.0f);
    float d1 = u * p;                            // signed dphi in folded frame

    // net reflection sign: (x<0) xor (y<0) xor (ay>ax)
    unsigned sb = (__float_as_uint(x0) ^ __float_as_uint(y0)) & 0x80000000u;
    if (ay > ax) sb ^= 0x80000000u;
    float dphi = __uint_as_float(__float_as_uint(d1) ^ sb);

    float ad = fabsf(dphi);
    float t  = __saturatef(fmaf(-inv_band, ad, 3.0f));   // (P-inner)*inv_band == 3
    float tt = t * t;
    float g  = tt * fmaf(-2.0f, t, 3.0f);        // smoothstep
    float gph = c3ib * fmaf(-t, t, t);           // 0.5*dg/dd = 3*inv_band*t*(1-t)

    float common = (b * dphi) * fmaf(-gph, ad, g);
    float coef   = fmaf(b * g, dphi * dphi, a);

    float cx = coef * x0;
    float cy = coef * y0;
    ox = fmaf(common,  y0, -cx);                 // -(coef*x - common*y)
    oy = fmaf(-common, x0, -cy);                 // -(coef*y + common*x)

    if (M == 0.0f) { ox = 0.0f; oy = 0.0f; }     // origin (both exactly zero)
}

__global__ void canyon_grad_k8_kernel(const float4* __restrict__ xy4,
                                      float4* __restrict__ out4,
                                      const float* __restrict__ xy,
                                      float* __restrict__ out,
                                      const float* __restrict__ a_ptr,
                                      const float* __restrict__ b_ptr,
                                      int n4, int ntot,
                                      float inv_band, float c3ib)
{
    int gid  = blockIdx.x * blockDim.x + threadIdx.x;
    int lane = threadIdx.x & 31;
    int wid  = gid >> 5;
    int base = wid * 128 + lane;    // warp covers float4s [wid*128, wid*128+128)

    // broadcast loads (single address) + clamp, amortized over 8 points
    float a = fminf(fmaxf(__ldg(a_ptr), 0.0f), 20.0f);
    float b = fminf(fmaxf(__ldg(b_ptr), 0.0f), 20.0f);

    if (base + 96 < n4) {
        // Hot path: all four in range. Back-to-back LDG.128 (MLP=4), then
        // 8 independent point computations, then 4 STG.128.
        float4 v0 = xy4[base];
        float4 v1 = xy4[base + 32];
        float4 v2 = xy4[base + 64];
        float4 v3 = xy4[base + 96];

        float4 r0, r1, r2, r3;
        point_grad_fast(v0.x, v0.y, a, b, inv_band, c3ib, r0.x, r0.y);
        point_grad_fast(v0.z, v0.w, a, b, inv_band, c3ib, r0.z, r0.w);
        point_grad_fast(v1.x, v1.y, a, b, inv_band, c3ib, r1.x, r1.y);
        point_grad_fast(v1.z, v1.w, a, b, inv_band, c3ib, r1.z, r1.w);
        point_grad_fast(v2.x, v2.y, a, b, inv_band, c3ib, r2.x, r2.y);
        point_grad_fast(v2.z, v2.w, a, b, inv_band, c3ib, r2.z, r2.w);
        point_grad_fast(v3.x, v3.y, a, b, inv_band, c3ib, r3.x, r3.y);
        point_grad_fast(v3.z, v3.w, a, b, inv_band, c3ib, r3.z, r3.w);

        out4[base]      = r0;
        out4[base + 32] = r1;
        out4[base + 64] = r2;
        out4[base + 96] = r3;
    } else {
        // Edge warp (cold): guarded per-float4 loop.
        #pragma unroll
        for (int j = 0; j < 4; j++) {
            int i = base + j * 32;
            if (i < n4) {
                float4 v = xy4[i];
                float4 r;
                point_grad_fast(v.x, v.y, a, b, inv_band, c3ib, r.x, r.y);
                point_grad_fast(v.z, v.w, a, b, inv_band, c3ib, r.z, r.w);
                out4[i] = r;
            }
        }
        // residual pair when ntot % 4 == 2 (N odd)
        if (gid == 0 && (ntot & 3)) {
            int e = n4 * 4;
            float ox, oy;
            point_grad_fast(xy[e], xy[e + 1], a, b, inv_band, c3ib, ox, oy);
            out[e] = ox; out[e + 1] = oy;
        }
    }
}

// ---------- generic fallback (any K), validated round-1 path ----------
__device__ __forceinline__ void point_grad_gen(float x, float y,
                                               float a, float b,
                                               float k_over_2pi, float step,
                                               float P, float inner, float inv_band,
                                               float& ox, float& oy)
{
    float phi = atan2f(y, x);
    if (phi < 0.0f) phi += 6.2831853071795864769f;
    float n    = rintf(phi * k_over_2pi);
    float dphi = fmaf(-n, step, phi);
    float d    = P - fabsf(dphi);
    float t = __saturatef((d - inner) * inv_band);
    float g  = t * t * (3.0f - 2.0f * t);
    float gp = 6.0f * t * (1.0f - t) * inv_band;
    float s     = (dphi >= 0.0f) ? -1.0f : 1.0f;
    float dphi2 = dphi * dphi;
    float common = 0.5f * b * (dphi2 * gp * s + 2.0f * g * dphi);
    float coef   = fmaf(b * g, dphi2, a);
    float gx = coef * x - common * y;
    float gy = coef * y + common * x;
    if (x == 0.0f && y == 0.0f) { gx = 0.0f; gy = 0.0f; }
    ox = -gx; oy = -gy;
}

__global__ void canyon_grad_gen_kernel(const float* __restrict__ xy,
                                       float* __restrict__ out,
                                       const float* __restrict__ a_ptr,
                                       const float* __restrict__ b_ptr,
                                       int ntot,
                                       float k_over_2pi, float step,
                                       float P, float inner, float inv_band)
{
    int i = blockIdx.x * blockDim.x + threadIdx.x;
    int base = i * 4;
    if (base >= ntot) return;
    float a = fminf(fmaxf(__ldg(a_ptr), 0.0f), 20.0f);
    float b = fminf(fmaxf(__ldg(b_ptr), 0.0f), 20.0f);
    if (base + 3 < ntot) {
        float4 v = *reinterpret_cast<const float4*>(xy + base);
        float4 r;
        point_grad_gen(v.x, v.y, a, b, k_over_2pi, step, P, inner, inv_band, r.x, r.y);
        point_grad_gen(v.z, v.w, a, b, k_over_2pi, step, P, inner, inv_band, r.z, r.w);
        *reinterpret_cast<float4*>(out + base) = r;
    } else {
        for (int e = base; e + 1 < ntot; e += 2) {
            float ox, oy;
            point_grad_gen(xy[e], xy[e + 1], a, b, k_over_2pi, step, P, inner, inv_band, ox, oy);
            out[e] = ox; out[e + 1] = oy;
        }
    }
}

extern "C" void kernel_launch(void* const* d_in, const int* in_sizes, int n_in,
                              void* d_out, int out_size)
{
    const float* xy    = (const float*)d_in[0];
    const float* a_ptr = (const float*)d_in[2];
    const float* b_ptr = (const float*)d_in[3];
    float* out         = (float*)d_out;

    int ntot = in_sizes[0];
    int K    = in_sizes[1];

    double PI = 3.14159265358979323846;
    float P        = (float)(PI / (double)K);
    float inner    = (float)(PI / (4.0 * (double)K));
    float inv_band = (float)(4.0 * (double)K / PI);
    float c3ib     = 3.0f * inv_band;

    if (K == 8) {
        int n4 = ntot >> 2;                          // whole float4s
        int nwarp = (n4 + 127) / 128;                // 128 float4s per warp
        long long nthreads = (long long)nwarp * 32;
        if (nthreads == 0) nthreads = 32;            // residual-only case
        int threads = 256;
        int blocks  = (int)((nthreads + threads - 1) / threads);

        canyon_grad_k8_kernel<<<blocks, threads>>>(
            (const float4*)xy, (float4*)out, xy, out, a_ptr, b_ptr,
            n4, ntot, inv_band, c3ib);
    } else {
        float k_over_2pi = (float)((double)K / (2.0 * PI));
        float step       = (float)(2.0 * PI / (double)K);
        int n4      = (ntot + 3) / 4;
        int threads = 256;
        int blocks  = (n4 + threads - 1) / threads;
        canyon_grad_gen_kernel<<<blocks, threads>>>(xy, out, a_ptr, b_ptr, ntot,
                                                    k_over_2pi, step, P, inner, inv_band);
    }
}

// round 14
// speedup vs baseline: 1.4975x; 1.0694x over previous
#include <cuda_runtime.h>
#include <math.h>

// Analytic gradient of the "canyon" potential (round-1 derivation, validated):
//   coef   = a + b*g*dphi^2
//   common = b*dphi*(g - 0.5*g'(d)*|dphi|)
//   out    = -(coef*x - common*y, coef*y + common*x), 0 at origin
//
// K==8 fast path. Fold to the first octant with abs/min/max: each reflection
// used (x<0, y<0, swap when |y|>|x|) is about a multiple of the ray spacing
// pi/4, so each flips sign(dphi); net sign = XOR of three sign bits.
// If m > tan(22.5)*M use atan(u) - pi/4 = atan((m-M)/(m+M)) exactly, so a
// single division feeds one deg-9 odd poly on |u| <= tan(pi/8) (err <= 5.6e-6).
// t = saturate(3 - inv_band*|dphi|): (P-inner)*inv_band == 3 identically.
//
// R11: explicit 4x LDG.128 front-batching (MLP=4).
// R13: persistent single-wave grid (152 SMs x 7 CTAs) + grid-stride —
//      removes ~4 wave ramp/drain transitions that held achieved occ at 57%.

__device__ __forceinline__ void point_grad_fast(float x0, float y0,
                                                float a, float b,
                                                float inv_band, float c3ib,
                                                float& ox, float& oy)
{
    const float T22 = 0.41421356237309504880f;   // tan(pi/8)

    float ax = fabsf(x0);
    float ay = fabsf(y0);
    float M  = fmaxf(ax, ay);
    float m  = fminf(ax, ay);

    // second fold via atan identity: atan(m/M) - pi/4 = atan((m-M)/(m+M))
    bool  c   = m > T22 * M;
    float num = c ? (m - M) : m;
    float den = c ? (m + M) : M;

    float u  = __fdividef(num, den);             // |u| <= tan(pi/8)
    float u2 = u * u;
    float p  = fmaf(u2, fmaf(u2, fmaf(u2, fmaf(u2, 0.11111111f, -0.14285714f),
                                      0.2f), -0.33333333f), 1.0f);
    float d1 = u * p;                            // signed dphi in folded frame

    // net reflection sign: (x<0) xor (y<0) xor (ay>ax)
    unsigned sb = (__float_as_uint(x0) ^ __float_as_uint(y0)) & 0x80000000u;
    if (ay > ax) sb ^= 0x80000000u;
    float dphi = __uint_as_float(__float_as_uint(d1) ^ sb);

    float ad = fabsf(dphi);
    float t  = __saturatef(fmaf(-inv_band, ad, 3.0f));   // (P-inner)*inv_band == 3
    float tt = t * t;
    float g  = tt * fmaf(-2.0f, t, 3.0f);        // smoothstep
    float gph = c3ib * fmaf(-t, t, t);           // 0.5*dg/dd = 3*inv_band*t*(1-t)

    float common = (b * dphi) * fmaf(-gph, ad, g);
    float coef   = fmaf(b * g, dphi * dphi, a);

    float cx = coef * x0;
    float cy = coef * y0;
    ox = fmaf(common,  y0, -cx);                 // -(coef*x - common*y)
    oy = fmaf(-common, x0, -cy);                 // -(coef*y + common*x)

    if (M == 0.0f) { ox = 0.0f; oy = 0.0f; }     // origin (both exactly zero)
}

__global__ void __launch_bounds__(256, 7)
canyon_grad_k8_kernel(const float4* __restrict__ xy4,
                      float4* __restrict__ out4,
                      const float* __restrict__ xy,
                      float* __restrict__ out,
                      const float* __restrict__ a_ptr,
                      const float* __restrict__ b_ptr,
                      int n4, int ntot, int nthreads,
                      float inv_band, float c3ib)
{
    int gid = blockIdx.x * blockDim.x + threadIdx.x;
    int T   = nthreads;

    // broadcast loads (single address) + clamp, amortized over all work
    float a = fminf(fmaxf(__ldg(a_ptr), 0.0f), 20.0f);
    float b = fminf(fmaxf(__ldg(b_ptr), 0.0f), 20.0f);

    int i = gid;
    // Hot loop: 4 back-to-back LDG.128 (MLP=4), 8 point computations, 4 STG.128.
    for (; i + 3 * T < n4; i += 4 * T) {
        float4 v0 = xy4[i];
        float4 v1 = xy4[i + T];
        float4 v2 = xy4[i + 2 * T];
        float4 v3 = xy4[i + 3 * T];

        float4 r0, r1, r2, r3;
        point_grad_fast(v0.x, v0.y, a, b, inv_band, c3ib, r0.x, r0.y);
        point_grad_fast(v0.z, v0.w, a, b, inv_band, c3ib, r0.z, r0.w);
        point_grad_fast(v1.x, v1.y, a, b, inv_band, c3ib, r1.x, r1.y);
        point_grad_fast(v1.z, v1.w, a, b, inv_band, c3ib, r1.z, r1.w);
        point_grad_fast(v2.x, v2.y, a, b, inv_band, c3ib, r2.x, r2.y);
        point_grad_fast(v2.z, v2.w, a, b, inv_band, c3ib, r2.z, r2.w);
        point_grad_fast(v3.x, v3.y, a, b, inv_band, c3ib, r3.x, r3.y);
        point_grad_fast(v3.z, v3.w, a, b, inv_band, c3ib, r3.z, r3.w);

        out4[i]         = r0;
        out4[i + T]     = r1;
        out4[i + 2 * T] = r2;
        out4[i + 3 * T] = r3;
    }
    // Remainder: strided single-float4 iterations (cold, <=3 per thread).
    for (; i < n4; i += T) {
        float4 v = xy4[i];
        float4 r;
        point_grad_fast(v.x, v.y, a, b, inv_band, c3ib, r.x, r.y);
        point_grad_fast(v.z, v.w, a, b, inv_band, c3ib, r.z, r.w);
        out4[i] = r;
    }
    // residual pair when ntot % 4 == 2 (N odd)
    if (gid == 0 && (ntot & 3)) {
        int e = n4 * 4;
        float ox, oy;
        point_grad_fast(xy[e], xy[e + 1], a, b, inv_band, c3ib, ox, oy);
        out[e] = ox; out[e + 1] = oy;
    }
}

// ---------- generic fallback (any K), validated round-1 path ----------
__device__ __forceinline__ void point_grad_gen(float x, float y,
                                               float a, float b,
                                               float k_over_2pi, float step,
                                               float P, float inner, float inv_band,
                                               float& ox, float& oy)
{
    float phi = atan2f(y, x);
    if (phi < 0.0f) phi += 6.2831853071795864769f;
    float n    = rintf(phi * k_over_2pi);
    float dphi = fmaf(-n, step, phi);
    float d    = P - fabsf(dphi);
    float t = __saturatef((d - inner) * inv_band);
    float g  = t * t * (3.0f - 2.0f * t);
    float gp = 6.0f * t * (1.0f - t) * inv_band;
    float s     = (dphi >= 0.0f) ? -1.0f : 1.0f;
    float dphi2 = dphi * dphi;
    float common = 0.5f * b * (dphi2 * gp * s + 2.0f * g * dphi);
    float coef   = fmaf(b * g, dphi2, a);
    float gx = coef * x - common * y;
    float gy = coef * y + common * x;
    if (x == 0.0f && y == 0.0f) { gx = 0.0f; gy = 0.0f; }
    ox = -gx; oy = -gy;
}

__global__ void canyon_grad_gen_kernel(const float* __restrict__ xy,
                                       float* __restrict__ out,
                                       const float* __restrict__ a_ptr,
                                       const float* __restrict__ b_ptr,
                                       int ntot,
                                       float k_over_2pi, float step,
                                       float P, float inner, float inv_band)
{
    int i = blockIdx.x * blockDim.x + threadIdx.x;
    int base = i * 4;
    if (base >= ntot) return;
    float a = fminf(fmaxf(__ldg(a_ptr), 0.0f), 20.0f);
    float b = fminf(fmaxf(__ldg(b_ptr), 0.0f), 20.0f);
    if (base + 3 < ntot) {
        float4 v = *reinterpret_cast<const float4*>(xy + base);
        float4 r;
        point_grad_gen(v.x, v.y, a, b, k_over_2pi, step, P, inner, inv_band, r.x, r.y);
        point_grad_gen(v.z, v.w, a, b, k_over_2pi, step, P, inner, inv_band, r.z, r.w);
        *reinterpret_cast<float4*>(out + base) = r;
    } else {
        for (int e = base; e + 1 < ntot; e += 2) {
            float ox, oy;
            point_grad_gen(xy[e], xy[e + 1], a, b, k_over_2pi, step, P, inner, inv_band, ox, oy);
            out[e] = ox; out[e + 1] = oy;
        }
    }
}

extern "C" void kernel_launch(void* const* d_in, const int* in_sizes, int n_in,
                              void* d_out, int out_size)
{
    const float* xy    = (const float*)d_in[0];
    const float* a_ptr = (const float*)d_in[2];
    const float* b_ptr = (const float*)d_in[3];
    float* out         = (float*)d_out;

    int ntot = in_sizes[0];
    int K    = in_sizes[1];

    double PI = 3.14159265358979323846;
    float P        = (float)(PI / (double)K);
    float inner    = (float)(PI / (4.0 * (double)K));
    float inv_band = (float)(4.0 * (double)K / PI);
    float c3ib     = 3.0f * inv_band;

    if (K == 8) {
        int n4 = ntot >> 2;                    // whole float4s
        const int threads = 256;
        int blocks = 152 * 7;                  // one persistent wave on GB300
        int nthreads = blocks * threads;

        canyon_grad_k8_kernel<<<blocks, threads>>>(
            (const float4*)xy, (float4*)out, xy, out, a_ptr, b_ptr,
            n4, ntot, nthreads, inv_band, c3ib);
    } else {
        float k_over_2pi = (float)((double)K / (2.0 * PI));
        float step       = (float)(2.0 * PI / (double)K);
        int n4      = (ntot + 3) / 4;
        int threads = 256;
        int blocks  = (n4 + threads - 1) / threads;
        canyon_grad_gen_kernel<<<blocks, threads>>>(xy, out, a_ptr, b_ptr, ntot,
                                                    k_over_2pi, step, P, inner, inv_band);
    }
}

// round 17
// speedup vs baseline: 1.5225x; 1.0167x over previous
#include <cuda_runtime.h>
#include <math.h>

// Analytic gradient of the "canyon" potential (round-1 derivation, validated):
//   coef   = a + b*g*dphi^2
//   common = b*dphi*(g - 0.5*g'(d)*|dphi|)
//   out    = -(coef*x - common*y, coef*y + common*x), 0 at origin
//
// K==8 fast path: octant fold via abs/min/max (net sign = XOR of 3 reflection
// signs), atan identity atan(m/M)-pi/4 = atan((m-M)/(m+M)) for the upper half,
// one __fdividef + deg-9 odd poly on |u| <= tan(pi/8) (err <= 5.6e-6).
// t = saturate(3 - inv_band*|dphi|): (P-inner)*inv_band == 3 identically.
//
// R11: explicit 4x LDG.128 batching (MLP=4).
// R13: persistent single-wave grid.
// R15: software pipeline — prefetch next batch before computing current, so
//      cross-iteration LDG latency hides under compute (issue was 62% with
//      38% long-scoreboard idle; batch-at-a-time exposed one memory round
//      trip per iteration).

__device__ __forceinline__ void point_grad_fast(float x0, float y0,
                                                float a, float b,
                                                float inv_band, float c3ib,
                                                float& ox, float& oy)
{
    const float T22 = 0.41421356237309504880f;   // tan(pi/8)

    float ax = fabsf(x0);
    float ay = fabsf(y0);
    float M  = fmaxf(ax, ay);
    float m  = fminf(ax, ay);

    // second fold via atan identity: atan(m/M) - pi/4 = atan((m-M)/(m+M))
    bool  c   = m > T22 * M;
    float num = c ? (m - M) : m;
    float den = c ? (m + M) : M;

    float u  = __fdividef(num, den);             // |u| <= tan(pi/8)
    float u2 = u * u;
    float p  = fmaf(u2, fmaf(u2, fmaf(u2, fmaf(u2, 0.11111111f, -0.14285714f),
                                      0.2f), -0.33333333f), 1.0f);
    float d1 = u * p;                            // signed dphi in folded frame

    // net reflection sign: (x<0) xor (y<0) xor (ay>ax)
    unsigned sb = (__float_as_uint(x0) ^ __float_as_uint(y0)) & 0x80000000u;
    if (ay > ax) sb ^= 0x80000000u;
    float dphi = __uint_as_float(__float_as_uint(d1) ^ sb);

    float ad = fabsf(dphi);
    float t  = __saturatef(fmaf(-inv_band, ad, 3.0f));   // (P-inner)*inv_band == 3
    float tt = t * t;
    float g  = tt * fmaf(-2.0f, t, 3.0f);        // smoothstep
    float gph = c3ib * fmaf(-t, t, t);           // 0.5*dg/dd = 3*inv_band*t*(1-t)

    float common = (b * dphi) * fmaf(-gph, ad, g);
    float coef   = fmaf(b * g, dphi * dphi, a);

    float cx = coef * x0;
    float cy = coef * y0;
    ox = fmaf(common,  y0, -cx);                 // -(coef*x - common*y)
    oy = fmaf(-common, x0, -cy);                 // -(coef*y + common*x)

    if (M == 0.0f) { ox = 0.0f; oy = 0.0f; }     // origin (both exactly zero)
}

__device__ __forceinline__ float4 quad_grad(float4 v, float a, float b,
                                            float inv_band, float c3ib)
{
    float4 r;
    point_grad_fast(v.x, v.y, a, b, inv_band, c3ib, r.x, r.y);
    point_grad_fast(v.z, v.w, a, b, inv_band, c3ib, r.z, r.w);
    return r;
}

__global__ void __launch_bounds__(256, 6)
canyon_grad_k8_kernel(const float4* __restrict__ xy4,
                      float4* __restrict__ out4,
                      const float* __restrict__ xy,
                      float* __restrict__ out,
                      const float* __restrict__ a_ptr,
                      const float* __restrict__ b_ptr,
                      int n4, int ntot, int nthreads,
                      float inv_band, float c3ib)
{
    int gid = blockIdx.x * blockDim.x + threadIdx.x;
    int T   = nthreads;

    float a = fminf(fmaxf(__ldg(a_ptr), 0.0f), 20.0f);
    float b = fminf(fmaxf(__ldg(b_ptr), 0.0f), 20.0f);

    int i = gid;
    if (i + 3 * T < n4) {
        // prologue: load batch 0
        float4 v0 = xy4[i];
        float4 v1 = xy4[i + T];
        float4 v2 = xy4[i + 2 * T];
        float4 v3 = xy4[i + 3 * T];

        int inext = i + 4 * T;
        while (inext + 3 * T < n4) {
            // prefetch next batch (hides its latency under current compute)
            float4 n0 = xy4[inext];
            float4 n1 = xy4[inext + T];
            float4 n2 = xy4[inext + 2 * T];
            float4 n3 = xy4[inext + 3 * T];

            // compute + store current batch (results reuse v registers)
            out4[i]         = quad_grad(v0, a, b, inv_band, c3ib);
            out4[i + T]     = quad_grad(v1, a, b, inv_band, c3ib);
            out4[i + 2 * T] = quad_grad(v2, a, b, inv_band, c3ib);
            out4[i + 3 * T] = quad_grad(v3, a, b, inv_band, c3ib);

            v0 = n0; v1 = n1; v2 = n2; v3 = n3;
            i = inext;
            inext += 4 * T;
        }
        // epilogue: last full batch
        out4[i]         = quad_grad(v0, a, b, inv_band, c3ib);
        out4[i + T]     = quad_grad(v1, a, b, inv_band, c3ib);
        out4[i + 2 * T] = quad_grad(v2, a, b, inv_band, c3ib);
        out4[i + 3 * T] = quad_grad(v3, a, b, inv_band, c3ib);
        i += 4 * T;
    }
    // cold tail: remaining single float4s for this thread
    for (; i < n4; i += T) {
        float4 v = xy4[i];
        out4[i] = quad_grad(v, a, b, inv_band, c3ib);
    }
    // residual pair when ntot % 4 == 2 (N odd)
    if (gid == 0 && (ntot & 3)) {
        int e = n4 * 4;
        float ox, oy;
        point_grad_fast(xy[e], xy[e + 1], a, b, inv_band, c3ib, ox, oy);
        out[e] = ox; out[e + 1] = oy;
    }
}

// ---------- generic fallback (any K), validated round-1 path ----------
__device__ __forceinline__ void point_grad_gen(float x, float y,
                                               float a, float b,
                                               float k_over_2pi, float step,
                                               float P, float inner, float inv_band,
                                               float& ox, float& oy)
{
    float phi = atan2f(y, x);
    if (phi < 0.0f) phi += 6.2831853071795864769f;
    float n    = rintf(phi * k_over_2pi);
    float dphi = fmaf(-n, step, phi);
    float d    = P - fabsf(dphi);
    float t = __saturatef((d - inner) * inv_band);
    float g  = t * t * (3.0f - 2.0f * t);
    float gp = 6.0f * t * (1.0f - t) * inv_band;
    float s     = (dphi >= 0.0f) ? -1.0f : 1.0f;
    float dphi2 = dphi * dphi;
    float common = 0.5f * b * (dphi2 * gp * s + 2.0f * g * dphi);
    float coef   = fmaf(b * g, dphi2, a);
    float gx = coef * x - common * y;
    float gy = coef * y + common * x;
    if (x == 0.0f && y == 0.0f) { gx = 0.0f; gy = 0.0f; }
    ox = -gx; oy = -gy;
}

__global__ void canyon_grad_gen_kernel(const float* __restrict__ xy,
                                       float* __restrict__ out,
                                       const float* __restrict__ a_ptr,
                                       const float* __restrict__ b_ptr,
                                       int ntot,
                                       float k_over_2pi, float step,
                                       float P, float inner, float inv_band)
{
    int i = blockIdx.x * blockDim.x + threadIdx.x;
    int base = i * 4;
    if (base >= ntot) return;
    float a = fminf(fmaxf(__ldg(a_ptr), 0.0f), 20.0f);
    float b = fminf(fmaxf(__ldg(b_ptr), 0.0f), 20.0f);
    if (base + 3 < ntot) {
        float4 v = *reinterpret_cast<const float4*>(xy + base);
        float4 r;
        point_grad_gen(v.x, v.y, a, b, k_over_2pi, step, P, inner, inv_band, r.x, r.y);
        point_grad_gen(v.z, v.w, a, b, k_over_2pi, step, P, inner, inv_band, r.z, r.w);
        *reinterpret_cast<float4*>(out + base) = r;
    } else {
        for (int e = base; e + 1 < ntot; e += 2) {
            float ox, oy;
            point_grad_gen(xy[e], xy[e + 1], a, b, k_over_2pi, step, P, inner, inv_band, ox, oy);
            out[e] = ox; out[e + 1] = oy;
        }
    }
}

extern "C" void kernel_launch(void* const* d_in, const int* in_sizes, int n_in,
                              void* d_out, int out_size)
{
    const float* xy    = (const float*)d_in[0];
    const float* a_ptr = (const float*)d_in[2];
    const float* b_ptr = (const float*)d_in[3];
    float* out         = (float*)d_out;

    int ntot = in_sizes[0];
    int K    = in_sizes[1];

    double PI = 3.14159265358979323846;
    float P        = (float)(PI / (double)K);
    float inner    = (float)(PI / (4.0 * (double)K));
    float inv_band = (float)(4.0 * (double)K / PI);
    float c3ib     = 3.0f * inv_band;

    if (K == 8) {
        int n4 = ntot >> 2;                    // whole float4s
        const int threads = 256;
        int blocks = 152 * 6;                  // one persistent wave @ 6 CTAs/SM
        int nthreads = blocks * threads;

        canyon_grad_k8_kernel<<<blocks, threads>>>(
            (const float4*)xy, (float4*)out, xy, out, a_ptr, b_ptr,
            n4, ntot, nthreads, inv_band, c3ib);
    } else {
        float k_over_2pi = (float)((double)K / (2.0 * PI));
        float step       = (float)(2.0 * PI / (double)K);
        int n4      = (ntot + 3) / 4;
        int threads = 256;
        int blocks  = (n4 + threads - 1) / threads;
        canyon_grad_gen_kernel<<<blocks, threads>>>(xy, out, a_ptr, b_ptr, ntot,
                                                    k_over_2pi, step, P, inner, inv_band);
    }
}